// round 10
// baseline (speedup 1.0000x reference)
#include <cuda_runtime.h>
#include <cuda_fp16.h>

// ForwardWarp: forward splatting with Gaussian softmax weights.
// img, counts: (8,1,720,1280) f32; flo: (8,2,720,1280) f32 (ch0 = y shifts W, ch1 = x shifts H)
// out: [0:S) = img_warp / (one_warp + eps), [S:2S) = one_warp
//
// Splat: one branchless red.global.add.noftz.v4.f16x2 per pixel into 4 parity copies
// (pr=ix1&1, pc=iy1&1), rowpair-interleaved layout (validated R8; at the LTS RED-quantum
// floor). Scratch is FULL-SIZE (per-image regions, 118MB): chunked splat/normalize order
// keeps each chunk's 29.6MB L2-hot, and zeroing collapses to one trailing memset.
// Normalize: 4-row x 2-col tiles (1.25x scratch over-read, ~60 regs -> ~50% occ).

static constexpr int N_ = 8;
static constexpr int H_ = 720;
static constexpr int W_ = 1280;
static constexpr int S_ = N_ * H_ * W_;     // 7,372,800
static constexpr float EPS_ = 1e-6f;

static constexpr int CHUNKS_ = 4;           // 2 images per chunk
static constexpr int PC_ = S_ / CHUNKS_;    // 1,843,200 pixels per chunk

static constexpr int NP_ = 361;             // pair-rows per copy per image (incl. pads)
static constexpr int WPAD_ = 2564;          // words per pair-row (16B multiple)
static constexpr int COPY_WORDS_ = NP_ * WPAD_;                 // per copy per image
static constexpr long long SCR_WORDS_ = 4LL * N_ * COPY_WORDS_; // 29,619,328 words = 118.5MB

__device__ __align__(16) unsigned int g_S[SCR_WORDS_];   // BSS zero; trailing memset restores

__device__ __forceinline__ void red_v4h2(unsigned int* p, unsigned int s0, unsigned int s1,
                                         unsigned int s2, unsigned int s3) {
    asm volatile("red.global.add.noftz.v4.f16x2 [%0], {%1, %2, %3, %4};"
                 :: "l"(p), "r"(s0), "r"(s1), "r"(s2), "r"(s3) : "memory");
}
__device__ __forceinline__ unsigned int pack_h2(float a, float b) {
    __half2 h = __float22half2_rn(make_float2(a, b));
    return *reinterpret_cast<unsigned int*>(&h);
}
__device__ __forceinline__ float2 unpack_h2(unsigned int u) {
    return __half22float2(*reinterpret_cast<__half2*>(&u));
}

__global__ void __launch_bounds__(256) splat_kernel(
    const float* __restrict__ img,
    const float* __restrict__ counts,
    const float* __restrict__ flo,
    int chunk)
{
    int idx = chunk * PC_ + blockIdx.x * blockDim.x + threadIdx.x;

    int w  = idx % W_;
    int hw = idx / W_;
    int h  = hw % H_;
    int n  = hw / H_;

    int flo_base = ((n * 2) * H_ + h) * W_ + w;
    float y = __ldcs(flo + flo_base);
    float x = __ldcs(flo + flo_base + H_ * W_);

    float im = __ldcs(img + idx);
    float c  = __ldcs(counts + idx);

    float x1 = floorf(x);
    float y1 = floorf(y);
    float fx = x - x1;
    float fy = y - y1;
    float gx = fx - 1.0f;
    float gy = fy - 1.0f;

    float dx1 = fx * fx, dx2 = gx * gx;
    float dy1 = fy * fy, dy2 = gy * gy;

    float w11 = __expf(-(dx1 + dy1));   // row ix1, col iy1
    float w12 = __expf(-(dx1 + dy2));   // row ix1, col iy2
    float w21 = __expf(-(dx2 + dy1));   // row ix2, col iy1
    float w22 = __expf(-(dx2 + dy2));   // row ix2, col iy2
    float inv = 1.0f / (w11 + w12 + w21 + w22);
    float cinv = c * inv;

    int ix1 = (int)x1 + h;
    int iy1 = (int)y1 + w;

    if (ix1 < -1 || ix1 > H_ - 1 || iy1 < -1 || iy1 > W_ - 1) return;

    int pr = ix1 & 1;                     // (-1 & 1) == 1
    int pc = iy1 & 1;
    int P  = (ix1 + pr) >> 1;
    int wv = 2 * iy1 + 2 * pc;

    unsigned int* p = g_S + (((long long)((pr * 2 + pc) * N_ + n) * NP_ + P) * WPAD_ + wv);

    // word order in footprint: [ (r1,c1), (r2,c1), (r1,c2), (r2,c2) ]
    red_v4h2(p,
             pack_h2(im * (w11 * cinv), w11 * cinv),
             pack_h2(im * (w21 * cinv), w21 * cinv),
             pack_h2(im * (w12 * cinv), w12 * cinv),
             pack_h2(im * (w22 * cinv), w22 * cinv));
}

// One thread per 4-row x 2-col output tile: rows 4r..4r+3, cols {2Y, 2Y+1}, image n.
// pr=0 copies: pairs 2r,2r+1 exactly; pr=1 copies: pairs 2r..2r+2 (edges half-used).
__global__ void __launch_bounds__(256) normalize_kernel(float* __restrict__ out, int chunk)
{
    int t = blockIdx.x * blockDim.x + threadIdx.x;   // 0 .. 230399 per chunk
    int Y  = t % (W_ / 2);          // 0..639
    int rm = t / (W_ / 2);
    int r  = rm % (H_ / 4);         // 0..179
    int ni = rm / (H_ / 4);         // 0..1
    int n  = chunk * 2 + ni;

    const unsigned int* c00 = g_S + (long long)((0 * N_) + n) * COPY_WORDS_;
    const unsigned int* c01 = g_S + (long long)((1 * N_) + n) * COPY_WORDS_;
    const unsigned int* c10 = g_S + (long long)((2 * N_) + n) * COPY_WORDS_;
    const unsigned int* c11 = g_S + (long long)((3 * N_) + n) * COPY_WORDS_;

    int q = 4 * Y;
    int p0 = 2 * r;                 // first pair index

    // ---- loads (all vector, streaming) ----
    uint4 v[2];                     // c00 pair p0+j
    uint2 u0[2], u1[2];             // c01 pair p0+j: col 2Y; col 2Y+1
    uint4 A[3];                     // c10 pair p0+k: [x=(2P-1,c0), y=(2P,c0), z=(2P-1,c1), w=(2P,c1)]
    uint2 E[3], G[3];               // c11 pair p0+k: col 2Y {x=(2P-1), y=(2P)}; col 2Y+1

    #pragma unroll
    for (int j = 0; j < 2; j++) {
        int row = (p0 + j) * WPAD_;
        v[j]  = __ldcs(reinterpret_cast<const uint4*>(c00 + row + q));
        u0[j] = __ldcs(reinterpret_cast<const uint2*>(c01 + row + q + 2));
        u1[j] = __ldcs(reinterpret_cast<const uint2*>(c01 + row + q + 4));
    }
    #pragma unroll
    for (int k = 0; k < 3; k++) {
        int row = (p0 + k) * WPAD_;
        A[k] = __ldcs(reinterpret_cast<const uint4*>(c10 + row + q));
        E[k] = __ldcs(reinterpret_cast<const uint2*>(c11 + row + q + 2));
        G[k] = __ldcs(reinterpret_cast<const uint2*>(c11 + row + q + 4));
    }

    // per-row word selection:
    // row 4r+0: v[0].x/.z, u0[0].x/u1[0].x, A[0].y/.w, E[0].y/G[0].y
    // row 4r+1: v[0].y/.w, u0[0].y/u1[0].y, A[1].x/.z, E[1].x/G[1].x
    // row 4r+2: v[1].x/.z, u0[1].x/u1[1].x, A[1].y/.w, E[1].y/G[1].y
    // row 4r+3: v[1].y/.w, u0[1].y/u1[1].y, A[2].x/.z, E[2].x/G[2].x
    unsigned int m00[4] = {v[0].x, v[0].y, v[1].x, v[1].y};
    unsigned int m00b[4] = {v[0].z, v[0].w, v[1].z, v[1].w};
    unsigned int m01[4] = {u0[0].x, u0[0].y, u0[1].x, u0[1].y};
    unsigned int m01b[4] = {u1[0].x, u1[0].y, u1[1].x, u1[1].y};
    unsigned int m10[4] = {A[0].y, A[1].x, A[1].y, A[2].x};
    unsigned int m10b[4] = {A[0].w, A[1].z, A[1].w, A[2].z};
    unsigned int m11[4] = {E[0].y, E[1].x, E[1].y, E[2].x};
    unsigned int m11b[4] = {G[0].y, G[1].x, G[1].y, G[2].x};

    int obase = ((n * H_) + 4 * r) * W_ + 2 * Y;

    #pragma unroll
    for (int i = 0; i < 4; i++) {
        float2 f0 = unpack_h2(m00[i]),  f1 = unpack_h2(m01[i]);
        float2 f2 = unpack_h2(m10[i]),  f3 = unpack_h2(m11[i]);
        float2 g0 = unpack_h2(m00b[i]), g1 = unpack_h2(m01b[i]);
        float2 g2 = unpack_h2(m10b[i]), g3 = unpack_h2(m11b[i]);

        float num0 = (f0.x + f1.x) + (f2.x + f3.x);
        float den0 = (f0.y + f1.y) + (f2.y + f3.y);
        float num1 = (g0.x + g1.x) + (g2.x + g3.x);
        float den1 = (g0.y + g1.y) + (g2.y + g3.y);

        int o = obase + i * W_;
        __stcs(reinterpret_cast<float2*>(out + o),
               make_float2(num0 / (den0 + EPS_), num1 / (den1 + EPS_)));
        __stcs(reinterpret_cast<float2*>(out + S_ + o),
               make_float2(den0, den1));
    }
}

extern "C" void kernel_launch(void* const* d_in, const int* in_sizes, int n_in,
                              void* d_out, int out_size)
{
    const float* img    = (const float*)d_in[0];
    const float* counts = (const float*)d_in[1];
    const float* flo    = (const float*)d_in[2];
    float* out = (float*)d_out;

    void* scr = nullptr;
    cudaGetSymbolAddress(&scr, g_S);

    int splat_blocks = PC_ / 256;                    // 7200
    int norm_blocks  = (PC_ / 8) / 256;              // 900 (8 cells per thread)

    for (int chunk = 0; chunk < CHUNKS_; chunk++) {
        splat_kernel<<<splat_blocks, 256>>>(img, counts, flo, chunk);
        normalize_kernel<<<norm_blocks, 256>>>(out, chunk);
    }
    // one trailing memset restores the all-zero invariant for the next graph replay
    cudaMemsetAsync(scr, 0, (size_t)SCR_WORDS_ * sizeof(unsigned int));
}

// round 11
// speedup vs baseline: 1.2921x; 1.2921x over previous
#include <cuda_runtime.h>
#include <cuda_fp16.h>

// ForwardWarp: forward splatting with Gaussian softmax weights.
// img, counts: (8,1,720,1280) f32; flo: (8,2,720,1280) f32 (ch0 = y shifts W, ch1 = x shifts H)
// out: [0:S) = img_warp / (one_warp + eps), [S:2S) = one_warp
//
// Splat (validated R8, at the ~1cyc/RED-lane LSU floor): one branchless
// red.global.add.noftz.v4.f16x2 per pixel into 4 parity copies (pr=ix1&1, pc=iy1&1),
// rowpair-interleaved layout. Scratch chunk-shared (29.6MB, L2-resident).
// Normalize: COLUMN SWEEP. Thread owns a column pair {2y,2y+1} and 4 pair-rows;
// marches down carrying the straddling pr=1 uint4 -> ~1.0x scratch read, and
// zero-stores exactly the words it consumed (word-disjoint across segments ->
// race-free) -> memset node deleted. Pad words are never read; left dirty.

static constexpr int N_ = 8;
static constexpr int H_ = 720;
static constexpr int W_ = 1280;
static constexpr int S_ = N_ * H_ * W_;     // 7,372,800
static constexpr float EPS_ = 1e-6f;

static constexpr int CHUNKS_ = 4;           // 2 images per chunk
static constexpr int PC_ = S_ / CHUNKS_;    // 1,843,200 pixels per chunk

static constexpr int NP_ = 361;             // pair-rows per copy per image (incl. pads)
static constexpr int WPAD_ = 2564;          // words per pair-row (16B multiple)
static constexpr int NPW_ = NP_ * WPAD_;    // words per copy per image
static constexpr int SCR_WORDS_ = 8 * NPW_; // 4 copies x 2 images = 29.6MB

__device__ __align__(16) unsigned int g_S[SCR_WORDS_];  // BSS zero; fused zero-stores restore

__device__ __forceinline__ void red_v4h2(unsigned int* p, unsigned int s0, unsigned int s1,
                                         unsigned int s2, unsigned int s3) {
    asm volatile("red.global.add.noftz.v4.f16x2 [%0], {%1, %2, %3, %4};"
                 :: "l"(p), "r"(s0), "r"(s1), "r"(s2), "r"(s3) : "memory");
}
__device__ __forceinline__ unsigned int pack_h2(float a, float b) {
    __half2 h = __float22half2_rn(make_float2(a, b));
    return *reinterpret_cast<unsigned int*>(&h);
}
__device__ __forceinline__ float2 unpack_h2(unsigned int u) {
    return __half22float2(*reinterpret_cast<__half2*>(&u));
}

__global__ void __launch_bounds__(256) splat_kernel(
    const float* __restrict__ img,
    const float* __restrict__ counts,
    const float* __restrict__ flo,
    int chunk)
{
    int idx = chunk * PC_ + blockIdx.x * blockDim.x + threadIdx.x;

    int w  = idx % W_;
    int hw = idx / W_;
    int h  = hw % H_;
    int n  = hw / H_;
    int ni = n & 1;                 // image within chunk

    int flo_base = ((n * 2) * H_ + h) * W_ + w;
    float y = __ldcs(flo + flo_base);
    float x = __ldcs(flo + flo_base + H_ * W_);

    float im = __ldcs(img + idx);
    float c  = __ldcs(counts + idx);

    float x1 = floorf(x);
    float y1 = floorf(y);
    float fx = x - x1;
    float fy = y - y1;
    float gx = fx - 1.0f;
    float gy = fy - 1.0f;

    float dx1 = fx * fx, dx2 = gx * gx;
    float dy1 = fy * fy, dy2 = gy * gy;

    float w11 = __expf(-(dx1 + dy1));   // row ix1, col iy1
    float w12 = __expf(-(dx1 + dy2));   // row ix1, col iy2
    float w21 = __expf(-(dx2 + dy1));   // row ix2, col iy1
    float w22 = __expf(-(dx2 + dy2));   // row ix2, col iy2
    float inv = 1.0f / (w11 + w12 + w21 + w22);
    float cinv = c * inv;

    int ix1 = (int)x1 + h;
    int iy1 = (int)y1 + w;

    if (ix1 < -1 || ix1 > H_ - 1 || iy1 < -1 || iy1 > W_ - 1) return;

    int pr = ix1 & 1;                     // (-1 & 1) == 1
    int pc = iy1 & 1;
    int P  = (ix1 + pr) >> 1;
    int wv = 2 * iy1 + 2 * pc;

    unsigned int* p = g_S + (((pr * 2 + pc) * 2 + ni) * NP_ + P) * WPAD_ + wv;

    // word order in footprint: [ (r1,c1), (r2,c1), (r1,c2), (r2,c2) ]
    red_v4h2(p,
             pack_h2(im * (w11 * cinv), w11 * cinv),
             pack_h2(im * (w21 * cinv), w21 * cinv),
             pack_h2(im * (w12 * cinv), w12 * cinv),
             pack_h2(im * (w22 * cinv), w22 * cinv));
}

// Column-sweep normalize. Thread owns cols {2y, 2y+1}, image ni, pair-rows
// [p0, p0+4). Step p finalizes output rows {2p, 2p+1}:
//   row 2p:   c00 pair p (.x,.z), c01 pair p u2s (.x), c10 pair p (.y,.w), c11 pair p u2s (.y)
//   row 2p+1: c00 pair p (.y,.w), c01 pair p u2s (.y), c10 pair p+1 (.x,.z), c11 pair p+1 u2s (.x)
// c10/c11 pair p0 is also read by the previous segment, and pair p0+4 by the next;
// each segment zero-stores ONLY the words it consumed (disjoint) -> race-free.
static constexpr int SEGS_ = 90;            // 360 pairs / 4 per segment

__global__ void __launch_bounds__(256) normalize_kernel(float* __restrict__ out, int chunk)
{
    int t = blockIdx.x * blockDim.x + threadIdx.x;  // 0 .. 115199 per chunk
    int y    = t % (W_ / 2);        // 0..639
    int rest = t / (W_ / 2);
    int seg  = rest % SEGS_;        // 0..89
    int ni   = rest / SEGS_;        // 0..1
    int n    = chunk * 2 + ni;
    int p0   = seg * 4;
    int q    = 4 * y;

    unsigned int* c00 = g_S + (0 + ni) * NPW_;
    unsigned int* c01 = g_S + (2 + ni) * NPW_;
    unsigned int* c10 = g_S + (4 + ni) * NPW_;
    unsigned int* c11 = g_S + (6 + ni) * NPW_;

    // prologue: carried pr=1 pair p0 (we consume only .y-side words of it)
    int rpro = p0 * WPAD_ + q;
    uint4 A  = *reinterpret_cast<uint4*>(c10 + rpro);
    uint2 E0 = *reinterpret_cast<uint2*>(c11 + rpro + 2);
    uint2 E1 = *reinterpret_cast<uint2*>(c11 + rpro + 4);

    const uint4 z4 = make_uint4(0u, 0u, 0u, 0u);
    const uint2 z2 = make_uint2(0u, 0u);

    #pragma unroll
    for (int i = 0; i < 4; i++) {
        int p   = p0 + i;
        int rp  = p * WPAD_ + q;
        int rp1 = rp + WPAD_;

        uint4 V  = *reinterpret_cast<uint4*>(c00 + rp);
        uint2 U0 = *reinterpret_cast<uint2*>(c01 + rp + 2);
        uint2 U1 = *reinterpret_cast<uint2*>(c01 + rp + 4);
        uint4 A2 = *reinterpret_cast<uint4*>(c10 + rp1);
        uint2 F0 = *reinterpret_cast<uint2*>(c11 + rp1 + 2);
        uint2 F1 = *reinterpret_cast<uint2*>(c11 + rp1 + 4);

        // row 2p:   c0 = V.x + U0.x + A.y + E0.y ;  c1 = V.z + U1.x + A.w + E1.y
        // row 2p+1: c0 = V.y + U0.y + A2.x + F0.x ; c1 = V.w + U1.y + A2.z + F1.x
        float2 a0 = unpack_h2(V.x),  a1 = unpack_h2(U0.x), a2 = unpack_h2(A.y),  a3 = unpack_h2(E0.y);
        float2 b0 = unpack_h2(V.z),  b1 = unpack_h2(U1.x), b2 = unpack_h2(A.w),  b3 = unpack_h2(E1.y);
        float2 d0 = unpack_h2(V.y),  d1 = unpack_h2(U0.y), d2 = unpack_h2(A2.x), d3 = unpack_h2(F0.x);
        float2 e0 = unpack_h2(V.w),  e1 = unpack_h2(U1.y), e2 = unpack_h2(A2.z), e3 = unpack_h2(F1.x);

        float numA = (a0.x + a1.x) + (a2.x + a3.x);
        float denA = (a0.y + a1.y) + (a2.y + a3.y);
        float numB = (b0.x + b1.x) + (b2.x + b3.x);
        float denB = (b0.y + b1.y) + (b2.y + b3.y);
        float numC = (d0.x + d1.x) + (d2.x + d3.x);
        float denC = (d0.y + d1.y) + (d2.y + d3.y);
        float numD = (e0.x + e1.x) + (e2.x + e3.x);
        float denD = (e0.y + e1.y) + (e2.y + e3.y);

        int o0 = ((n * H_) + 2 * p) * W_ + 2 * y;   // row 2p
        int o1 = o0 + W_;                            // row 2p+1
        *reinterpret_cast<float2*>(out + o0)      = make_float2(numA / (denA + EPS_), numB / (denB + EPS_));
        *reinterpret_cast<float2*>(out + o1)      = make_float2(numC / (denC + EPS_), numD / (denD + EPS_));
        *reinterpret_cast<float2*>(out + S_ + o0) = make_float2(denA, denB);
        *reinterpret_cast<float2*>(out + S_ + o1) = make_float2(denC, denD);

        // zero-restore pair p (c00/c01 fully owned by this step)
        *reinterpret_cast<uint4*>(c00 + rp)     = z4;
        *reinterpret_cast<uint2*>(c01 + rp + 2) = z2;
        *reinterpret_cast<uint2*>(c01 + rp + 4) = z2;
        if (i == 0) {
            // prologue pair: we consumed only the .y-side words
            c10[rp + 1] = 0u;  c10[rp + 3] = 0u;
            c11[rp + 3] = 0u;  c11[rp + 5] = 0u;
        } else {
            // interior pair: both word-sides consumed within this segment
            *reinterpret_cast<uint4*>(c10 + rp)     = z4;
            *reinterpret_cast<uint2*>(c11 + rp + 2) = z2;
            *reinterpret_cast<uint2*>(c11 + rp + 4) = z2;
        }

        A = A2; E0 = F0; E1 = F1;
    }

    // epilogue: pair p0+4 — we consumed only the .x-side words
    int re = (p0 + 4) * WPAD_ + q;
    c10[re]     = 0u;  c10[re + 2] = 0u;
    c11[re + 2] = 0u;  c11[re + 4] = 0u;
}

extern "C" void kernel_launch(void* const* d_in, const int* in_sizes, int n_in,
                              void* d_out, int out_size)
{
    const float* img    = (const float*)d_in[0];
    const float* counts = (const float*)d_in[1];
    const float* flo    = (const float*)d_in[2];
    float* out = (float*)d_out;

    int splat_blocks = PC_ / 256;                           // 7200
    int norm_blocks  = (W_ / 2) * SEGS_ * 2 / 256;          // 450

    for (int chunk = 0; chunk < CHUNKS_; chunk++) {
        splat_kernel<<<splat_blocks, 256>>>(img, counts, flo, chunk);
        normalize_kernel<<<norm_blocks, 256>>>(out, chunk);
    }
}